// round 14
// baseline (speedup 1.0000x reference)
#include <cuda_runtime.h>
#include <cstdint>

// Sliding-window gated attention (W=32, D=64) via tf32 mma.sync (sm_100-compatible).
// Per block: (b, h, 32 queries), 4 warps, each warp 8 queries x 40-col band.
// Staging converts to tf32 up front (LDG.128 -> cvt.rna -> STS.128); K is stored
// with columns interleaved per 8-group [0,4,1,5,2,6,3,7] so GEMM1 B-fragments
// load as LDS.64. Single barrier. GEMM2 reads V fragments as LDS.32, no cvt.

constexpr int B_ = 2, S_ = 2048, H_ = 8, D_ = 64, W_ = 32;
constexpr int HD = H_ * D_;
constexpr int TS   = 32;
constexpr int NT   = 128;
constexpr int ROWS = 64;
constexpr int KSTR = 72;           // K stride: LDS.64 conflict-free (36 = 4 mod 32)
constexpr int VSTR = 68;           // V stride: LDS.32 conflict-free (68 = 4 mod 32)
constexpr float SCALE = 0.125f;

constexpr int OFF_K = 0;
constexpr int SZ_K  = ROWS * KSTR;              // 4608
constexpr int OFF_V = OFF_K + SZ_K;
constexpr int SZ_V  = ROWS * VSTR;              // 4352
constexpr int OFF_A = OFF_V + SZ_V;
constexpr int SMEM_FLOATS = OFF_A + ROWS;       // 9024 floats = 36096 B -> 5 CTAs/SM

__device__ __forceinline__ float f2tf32(float x) {
    uint32_t r; asm("cvt.rna.tf32.f32 %0, %1;" : "=r"(r) : "f"(x));
    return __uint_as_float(r);
}
__device__ __forceinline__ uint32_t bits(float x) { return __float_as_uint(x); }
__device__ __forceinline__ uint32_t tfb(float x) {
    uint32_t r; asm("cvt.rna.tf32.f32 %0, %1;" : "=r"(r) : "f"(x));
    return r;
}

__device__ __forceinline__ void mma_tf32(float* d,
                                         uint32_t a0, uint32_t a1, uint32_t a2, uint32_t a3,
                                         uint32_t b0, uint32_t b1) {
    asm volatile("mma.sync.aligned.m16n8k8.row.col.f32.tf32.tf32.f32 "
                 "{%0,%1,%2,%3}, {%4,%5,%6,%7}, {%8,%9}, {%0,%1,%2,%3};"
                 : "+f"(d[0]), "+f"(d[1]), "+f"(d[2]), "+f"(d[3])
                 : "r"(a0), "r"(a1), "r"(a2), "r"(a3), "r"(b0), "r"(b1));
}

__global__ __launch_bounds__(NT, 5)
void swa_mma11_kernel(const float* __restrict__ qg,
                      const float* __restrict__ kg,
                      const float* __restrict__ vg,
                      const float* __restrict__ ag,
                      const float* __restrict__ bg,
                      float* __restrict__ outg)
{
    extern __shared__ float sm[];
    float* ks   = sm + OFF_K;
    float* vs   = sm + OFF_V;
    float* a_sm = sm + OFF_A;

    const int s0  = blockIdx.x * TS;
    const int h   = blockIdx.y;
    const int bb  = blockIdx.z;
    const int tid = threadIdx.x;
    const int lane = tid & 31;
    const int gid  = lane >> 2;
    const int tig  = lane & 3;
    const int qb   = (tid >> 5) * 8;       // warp's first local query
    const size_t headBase = (size_t)bb * S_ * HD + (size_t)h * D_;

    // ---- Q fragments from gmem (rows 0..7; LDGs issue early) ----
    const float* qrow0 = qg + headBase + (size_t)(s0 + qb + gid) * HD;
    uint32_t qa[8][2];
#pragma unroll
    for (int kk = 0; kk < 8; kk++) {
        const int c = kk * 8 + tig;
        qa[kk][0] = tfb(qrow0[c]);
        qa[kk][1] = tfb(qrow0[c + 4]);
    }
    const float bq0 = bg[((size_t)bb * S_ + (s0 + qb + gid)) * H_ + h];
    if (tid < ROWS) {
        const int j = s0 - (W_ - 1) + tid;
        a_sm[tid] = (j >= 0 && j < S_) ? ag[((size_t)bb * S_ + j) * H_ + h] : 0.f;
    }

    // ---- Stage K (permuted, tf32) and V (tf32): thread = (row, col-half) ----
    {
        const int r  = tid >> 1;           // 0..63
        const int ch = (tid & 1) * 32;     // column half base
        const int j  = s0 - (W_ - 1) + r;
        const bool ok = (j >= 0) && (j < S_);
        const float* krow = kg + headBase + (size_t)(ok ? j : 0) * HD + ch;
        const float* vrow = vg + headBase + (size_t)(ok ? j : 0) * HD + ch;
        float* kd = ks + r * KSTR + ch;
        float* vd = vs + r * VSTR + ch;
#pragma unroll
        for (int g = 0; g < 4; g++) {
            float4 f0, f1, w0, w1;
            if (ok) {
                f0 = *(const float4*)(krow + 8 * g);
                f1 = *(const float4*)(krow + 8 * g + 4);
                w0 = *(const float4*)(vrow + 8 * g);
                w1 = *(const float4*)(vrow + 8 * g + 4);
                f0.x = f2tf32(f0.x); f0.y = f2tf32(f0.y); f0.z = f2tf32(f0.z); f0.w = f2tf32(f0.w);
                f1.x = f2tf32(f1.x); f1.y = f2tf32(f1.y); f1.z = f2tf32(f1.z); f1.w = f2tf32(f1.w);
                w0.x = f2tf32(w0.x); w0.y = f2tf32(w0.y); w0.z = f2tf32(w0.z); w0.w = f2tf32(w0.w);
                w1.x = f2tf32(w1.x); w1.y = f2tf32(w1.y); w1.z = f2tf32(w1.z); w1.w = f2tf32(w1.w);
            } else {
                f0 = f1 = w0 = w1 = make_float4(0.f, 0.f, 0.f, 0.f);
            }
            // K columns interleaved: positions [0..7] = orig cols [0,4,1,5,2,6,3,7]
            *(float4*)(kd + 8 * g)     = make_float4(f0.x, f1.x, f0.y, f1.y);
            *(float4*)(kd + 8 * g + 4) = make_float4(f0.z, f1.z, f0.w, f1.w);
            *(float4*)(vd + 8 * g)     = w0;
            *(float4*)(vd + 8 * g + 4) = w1;
        }
    }
    __syncthreads();

    // ---- Gate factors: gf = SCALE*sigmoid(a_l*b_q)*mask (MUFU overlaps MMAs) ----
    float gf[5][2];
#pragma unroll
    for (int nt = 0; nt < 5; nt++) {
        const int colbase = nt * 8 + 2 * tig;
        const float a0 = a_sm[qb + colbase];
        const float a1 = a_sm[qb + colbase + 1];
#pragma unroll
        for (int e = 0; e < 2; e++) {
            const int col = colbase + e;
            const int l   = qb + col;
            const int j   = s0 - (W_ - 1) + l;
            const int d   = col - gid;
            const bool ok = (d >= 0) && (d < W_) && (j >= 0);
            const float av = e ? a1 : a0;
            const float g = __fdividef(SCALE, 1.f + __expf(-av * bq0));
            gf[nt][e] = ok ? g : 0.f;
        }
    }

    const uint32_t zr = 0u;

    // ---- GEMM1: S[8,40] = Q @ K^T; B fragments as LDS.64 from permuted K ----
    float acc[5][4] = {};
#pragma unroll
    for (int kk = 0; kk < 8; kk++) {
#pragma unroll
        for (int nt = 0; nt < 5; nt++) {
            const float2 kf = *(const float2*)(ks + (qb + nt * 8 + gid) * KSTR
                                               + kk * 8 + 2 * tig);
            mma_tf32(acc[nt], qa[kk][0], zr, qa[kk][1], zr,
                     bits(kf.x), bits(kf.y));
        }
    }

    // ---- Apply gates; D-frag -> A-frag via shuffles ----
    const int srcA = (lane & 28) | ((lane & 3) >> 1);
    const int srcB = srcA + 2;
    const bool odd = (lane & 1) != 0;
    uint32_t wa[5][2];
#pragma unroll
    for (int nt = 0; nt < 5; nt++) {
        const float w0 = f2tf32(acc[nt][0] * gf[nt][0]);
        const float w1 = f2tf32(acc[nt][1] * gf[nt][1]);
        const float s00 = __shfl_sync(0xffffffffu, w0, srcA);
        const float s10 = __shfl_sync(0xffffffffu, w1, srcA);
        const float s01 = __shfl_sync(0xffffffffu, w0, srcB);
        const float s11 = __shfl_sync(0xffffffffu, w1, srcB);
        wa[nt][0] = bits(odd ? s10 : s00);
        wa[nt][1] = bits(odd ? s11 : s01);
    }

    // ---- GEMM2: O[8,64] = W[8,40] @ V[40,64]; V pre-converted, no cvt ----
    float oacc[8][4] = {};
#pragma unroll
    for (int kk = 0; kk < 5; kk++) {
#pragma unroll
        for (int nt = 0; nt < 8; nt++) {
            const float* vp0 = vs + (qb + kk * 8 + tig) * VSTR + nt * 8 + gid;
            const float* vp1 = vp0 + 4 * VSTR;
            mma_tf32(oacc[nt], wa[kk][0], zr, wa[kk][1], zr,
                     bits(vp0[0]), bits(vp1[0]));
        }
    }

    // ---- Store O ----
    float* d0 = outg + headBase + (size_t)(s0 + qb + gid) * HD + 2 * tig;
#pragma unroll
    for (int nt = 0; nt < 8; nt++) {
        *(float2*)(d0 + nt * 8) = make_float2(oacc[nt][0], oacc[nt][1]);
    }
}

extern "C" void kernel_launch(void* const* d_in, const int* in_sizes, int n_in,
                              void* d_out, int out_size)
{
    const float* q = (const float*)d_in[0];
    const float* k = (const float*)d_in[1];
    const float* v = (const float*)d_in[2];
    const float* a = (const float*)d_in[3];
    const float* b = (const float*)d_in[4];
    float* out = (float*)d_out;

    const int smem = SMEM_FLOATS * (int)sizeof(float);   // 36096 B
    cudaFuncSetAttribute(swa_mma11_kernel,
                         cudaFuncAttributeMaxDynamicSharedMemorySize, smem);
    dim3 grid(S_ / TS, H_, B_);
    swa_mma11_kernel<<<grid, NT, smem>>>(q, k, v, a, b, out);
}

// round 15
// speedup vs baseline: 1.5341x; 1.5341x over previous
#include <cuda_runtime.h>
#include <cstdint>

// Sliding-window gated attention (W=32, D=64) via tf32 mma.sync (sm_100-compatible).
// Per block: (b, h, 32 queries), 4 warps, each warp 8 queries x 40-col band.
//   K: cp.async raw -> smem, inline rna cvt in GEMM1 fragments.
//   V: LDG (coalesced) -> cvt.rna -> STS (conflict-free) => GEMM2 has no cvt.
//   gates hoisted before GEMM1; D->A frag via shuffles; single barrier.
//   __launch_bounds__(128, 6) -> 24 warps/SM.

constexpr int B_ = 2, S_ = 2048, H_ = 8, D_ = 64, W_ = 32;
constexpr int HD = H_ * D_;
constexpr int TS   = 32;
constexpr int NT   = 128;
constexpr int ROWS = 64;
constexpr int STRIDE = 68;         // ≡4 mod 32: conflict-free LDS.32 frags + STS.128 staging
constexpr float SCALE = 0.125f;

constexpr int OFF_K = 0;
constexpr int SZ_K  = ROWS * STRIDE;            // 4352
constexpr int OFF_V = OFF_K + SZ_K;
constexpr int OFF_A = OFF_V + SZ_K;
constexpr int SMEM_FLOATS = OFF_A + ROWS;       // 8768 floats = 35072 B -> 6 CTAs/SM

__device__ __forceinline__ float f2tf32(float x) {
    uint32_t r; asm("cvt.rna.tf32.f32 %0, %1;" : "=r"(r) : "f"(x));
    return __uint_as_float(r);
}
__device__ __forceinline__ uint32_t bits(float x) { return __float_as_uint(x); }
__device__ __forceinline__ uint32_t tfb(float x) {
    uint32_t r; asm("cvt.rna.tf32.f32 %0, %1;" : "=r"(r) : "f"(x));
    return r;
}

__device__ __forceinline__ uint32_t smem_u32(const void* p) {
    uint32_t a;
    asm("{ .reg .u64 t; cvta.to.shared.u64 t, %1; cvt.u32.u64 %0, t; }" : "=r"(a) : "l"(p));
    return a;
}
__device__ __forceinline__ void cp16(uint32_t dst, const void* src, int srcsize) {
    asm volatile("cp.async.cg.shared.global [%0], [%1], 16, %2;"
                 :: "r"(dst), "l"(src), "r"(srcsize) : "memory");
}

__device__ __forceinline__ void mma_tf32(float* d,
                                         uint32_t a0, uint32_t a1, uint32_t a2, uint32_t a3,
                                         uint32_t b0, uint32_t b1) {
    asm volatile("mma.sync.aligned.m16n8k8.row.col.f32.tf32.tf32.f32 "
                 "{%0,%1,%2,%3}, {%4,%5,%6,%7}, {%8,%9}, {%0,%1,%2,%3};"
                 : "+f"(d[0]), "+f"(d[1]), "+f"(d[2]), "+f"(d[3])
                 : "r"(a0), "r"(a1), "r"(a2), "r"(a3), "r"(b0), "r"(b1));
}

__global__ __launch_bounds__(NT, 6)
void swa_mma12_kernel(const float* __restrict__ qg,
                      const float* __restrict__ kg,
                      const float* __restrict__ vg,
                      const float* __restrict__ ag,
                      const float* __restrict__ bg,
                      float* __restrict__ outg)
{
    extern __shared__ float sm[];
    float* ks   = sm + OFF_K;
    float* vs   = sm + OFF_V;
    float* a_sm = sm + OFF_A;
    const uint32_t smb = smem_u32(sm);

    const int s0  = blockIdx.x * TS;
    const int h   = blockIdx.y;
    const int bb  = blockIdx.z;
    const int tid = threadIdx.x;
    const int lane = tid & 31;
    const int gid  = lane >> 2;
    const int tig  = lane & 3;
    const int qb   = (tid >> 5) * 8;       // warp's first local query
    const size_t headBase = (size_t)bb * S_ * HD + (size_t)h * D_;

    // ---- Issue K staging via cp.async (raw fp32; zero-fill OOB rows) ----
#pragma unroll
    for (int i = 0; i < 8; i++) {
        const int idx = tid + i * NT;          // 0..1023
        const int r = idx >> 4, c4 = (idx & 15) << 2;
        const int j = s0 - (W_ - 1) + r;
        const bool ok = (j >= 0) && (j < S_);
        const int jc = ok ? j : 0;
        const size_t off = headBase + (size_t)jc * HD + c4;
        cp16(smb + (uint32_t)(OFF_K + r * STRIDE + c4) * 4u, kg + off, ok ? 16 : 0);
    }
    asm volatile("cp.async.commit_group;" ::: "memory");

    // ---- V staging: coalesced LDG -> cvt.rna -> conflict-free STS.128 ----
    // lanes 0-15 of a warp cover one row's 64 floats (256B contiguous): coalesced.
    // STS banks per 8-lane phase: c4 mod 32 covers 0..28 step 4: conflict-free.
#pragma unroll
    for (int i = 0; i < 8; i++) {
        const int idx = tid + i * NT;
        const int r = idx >> 4, c4 = (idx & 15) << 2;
        const int j = s0 - (W_ - 1) + r;
        const bool ok = (j >= 0) && (j < S_);
        float4 f = make_float4(0.f, 0.f, 0.f, 0.f);
        if (ok) f = *(const float4*)(vg + headBase + (size_t)j * HD + c4);
        f.x = f2tf32(f.x); f.y = f2tf32(f.y); f.z = f2tf32(f.z); f.w = f2tf32(f.w);
        *(float4*)(vs + r * STRIDE + c4) = f;
    }

    // ---- Q fragments from gmem (rows 0..7) ----
    const float* qrow0 = qg + headBase + (size_t)(s0 + qb + gid) * HD;
    uint32_t qa[8][2];
#pragma unroll
    for (int kk = 0; kk < 8; kk++) {
        const int c = kk * 8 + tig;
        qa[kk][0] = tfb(qrow0[c]);
        qa[kk][1] = tfb(qrow0[c + 4]);
    }
    const float bq0 = bg[((size_t)bb * S_ + (s0 + qb + gid)) * H_ + h];
    if (tid < ROWS) {
        const int j = s0 - (W_ - 1) + tid;
        a_sm[tid] = (j >= 0 && j < S_) ? ag[((size_t)bb * S_ + j) * H_ + h] : 0.f;
    }

    // ---- K ready; single barrier publishes K, V (STS), a_sm ----
    asm volatile("cp.async.wait_group 0;" ::: "memory");
    __syncthreads();

    // ---- Gate factors BEFORE GEMM1: gf = SCALE*sigmoid(a_l*b_q)*mask ----
    float gf[5][2];
#pragma unroll
    for (int nt = 0; nt < 5; nt++) {
        const int colbase = nt * 8 + 2 * tig;
        const float a0 = a_sm[qb + colbase];
        const float a1 = a_sm[qb + colbase + 1];
#pragma unroll
        for (int e = 0; e < 2; e++) {
            const int col = colbase + e;
            const int l   = qb + col;
            const int j   = s0 - (W_ - 1) + l;
            const int d   = col - gid;
            const bool ok = (d >= 0) && (d < W_) && (j >= 0);
            const float av = e ? a1 : a0;
            const float g = __fdividef(SCALE, 1.f + __expf(-av * bq0));
            gf[nt][e] = ok ? g : 0.f;
        }
    }

    const uint32_t zr = 0u;   // zero operand for unused fragment rows 8..15

    // ---- GEMM1: S[8,40] = Q @ K^T (inline cvt of raw K fragments) ----
    float acc[5][4] = {};
#pragma unroll
    for (int kk = 0; kk < 8; kk++) {
#pragma unroll
        for (int nt = 0; nt < 5; nt++) {
            const float* kp = ks + (qb + nt * 8 + gid) * STRIDE + kk * 8 + tig;
            mma_tf32(acc[nt], qa[kk][0], zr, qa[kk][1], zr,
                     tfb(kp[0]), tfb(kp[4]));
        }
    }

    // ---- Apply gates; D-frag -> A-frag via shuffles (rows 0..7) ----
    const int srcA = (lane & 28) | ((lane & 3) >> 1);
    const int srcB = srcA + 2;
    const bool odd = (lane & 1) != 0;
    uint32_t wa[5][2];
#pragma unroll
    for (int nt = 0; nt < 5; nt++) {
        const float w0 = f2tf32(acc[nt][0] * gf[nt][0]);
        const float w1 = f2tf32(acc[nt][1] * gf[nt][1]);
        const float s00 = __shfl_sync(0xffffffffu, w0, srcA);
        const float s10 = __shfl_sync(0xffffffffu, w1, srcA);
        const float s01 = __shfl_sync(0xffffffffu, w0, srcB);
        const float s11 = __shfl_sync(0xffffffffu, w1, srcB);
        wa[nt][0] = bits(odd ? s10 : s00);    // W[gid][nt*8+tig]
        wa[nt][1] = bits(odd ? s11 : s01);    // W[gid][nt*8+tig+4]
    }

    // ---- GEMM2: O[8,64] = W[8,40] @ V[40,64]; V pre-converted (no cvt) ----
    float oacc[8][4] = {};
#pragma unroll
    for (int kk = 0; kk < 5; kk++) {
#pragma unroll
        for (int nt = 0; nt < 8; nt++) {
            const float* vp0 = vs + (qb + kk * 8 + tig) * STRIDE + nt * 8 + gid;
            const float* vp1 = vp0 + 4 * STRIDE;
            mma_tf32(oacc[nt], wa[kk][0], zr, wa[kk][1], zr,
                     bits(vp0[0]), bits(vp1[0]));
        }
    }

    // ---- Store O (rows 0..7 of each fragment) ----
    float* d0 = outg + headBase + (size_t)(s0 + qb + gid) * HD + 2 * tig;
#pragma unroll
    for (int nt = 0; nt < 8; nt++) {
        *(float2*)(d0 + nt * 8) = make_float2(oacc[nt][0], oacc[nt][1]);
    }
}

extern "C" void kernel_launch(void* const* d_in, const int* in_sizes, int n_in,
                              void* d_out, int out_size)
{
    const float* q = (const float*)d_in[0];
    const float* k = (const float*)d_in[1];
    const float* v = (const float*)d_in[2];
    const float* a = (const float*)d_in[3];
    const float* b = (const float*)d_in[4];
    float* out = (float*)d_out;

    const int smem = SMEM_FLOATS * (int)sizeof(float);   // 35072 B
    cudaFuncSetAttribute(swa_mma12_kernel,
                         cudaFuncAttributeMaxDynamicSharedMemorySize, smem);
    dim3 grid(S_ / TS, H_, B_);
    swa_mma12_kernel<<<grid, NT, smem>>>(q, k, v, a, b, out);
}

// round 16
// speedup vs baseline: 1.6816x; 1.0962x over previous
#include <cuda_runtime.h>
#include <cstdint>

// Sliding-window gated attention (W=32, D=64) via tf32 mma.sync (sm_100-compatible).
// Per block: (b, h, 32 queries), 4 warps, each warp 8 queries x 40-col band
// (m16n8k8 fragments with upper 8 rows zero).
//   stage: cp.async K (group A), V (group B) -> smem (raw fp32)
//   wait K -> gate factors (hoisted) -> GEMM1 (inline rna cvt)
//   apply gates, D->A frag via shuffles
//   wait V -> GEMM2 (inline cvt)
// __launch_bounds__(128, 6) -> 24 warps/SM.

constexpr int B_ = 2, S_ = 2048, H_ = 8, D_ = 64, W_ = 32;
constexpr int HD = H_ * D_;
constexpr int TS   = 32;
constexpr int NT   = 128;
constexpr int ROWS = 64;           // 63 needed, 64 for even split
constexpr int STRIDE = 68;         // conflict-free: (gid*68+tig) mod 32 = 4*gid+tig
constexpr float SCALE = 0.125f;

constexpr int OFF_K = 0;
constexpr int SZ_K  = ROWS * STRIDE;            // 4352
constexpr int OFF_V = OFF_K + SZ_K;
constexpr int OFF_A = OFF_V + SZ_K;
constexpr int SMEM_FLOATS = OFF_A + ROWS;       // 8768 floats = 35072 B -> 6 CTAs/SM

__device__ __forceinline__ float f2tf32(float x) {
    uint32_t r; asm("cvt.rna.tf32.f32 %0, %1;" : "=r"(r) : "f"(x));
    return __uint_as_float(r);
}
__device__ __forceinline__ uint32_t bits(float x) { return __float_as_uint(x); }
__device__ __forceinline__ uint32_t tfb(float x) {          // rna tf32 bits
    uint32_t r; asm("cvt.rna.tf32.f32 %0, %1;" : "=r"(r) : "f"(x));
    return r;
}

__device__ __forceinline__ uint32_t smem_u32(const void* p) {
    uint32_t a;
    asm("{ .reg .u64 t; cvta.to.shared.u64 t, %1; cvt.u32.u64 %0, t; }" : "=r"(a) : "l"(p));
    return a;
}
__device__ __forceinline__ void cp16(uint32_t dst, const void* src, int srcsize) {
    asm volatile("cp.async.cg.shared.global [%0], [%1], 16, %2;"
                 :: "r"(dst), "l"(src), "r"(srcsize) : "memory");
}

__device__ __forceinline__ void mma_tf32(float* d,
                                         uint32_t a0, uint32_t a1, uint32_t a2, uint32_t a3,
                                         uint32_t b0, uint32_t b1) {
    asm volatile("mma.sync.aligned.m16n8k8.row.col.f32.tf32.tf32.f32 "
                 "{%0,%1,%2,%3}, {%4,%5,%6,%7}, {%8,%9}, {%0,%1,%2,%3};"
                 : "+f"(d[0]), "+f"(d[1]), "+f"(d[2]), "+f"(d[3])
                 : "r"(a0), "r"(a1), "r"(a2), "r"(a3), "r"(b0), "r"(b1));
}

__global__ __launch_bounds__(NT, 6)
void swa_mma13_kernel(const float* __restrict__ qg,
                      const float* __restrict__ kg,
                      const float* __restrict__ vg,
                      const float* __restrict__ ag,
                      const float* __restrict__ bg,
                      float* __restrict__ outg)
{
    extern __shared__ float sm[];
    float* ks   = sm + OFF_K;
    float* vs   = sm + OFF_V;
    float* a_sm = sm + OFF_A;
    const uint32_t smb = smem_u32(sm);

    const int s0  = blockIdx.x * TS;
    const int h   = blockIdx.y;
    const int bb  = blockIdx.z;
    const int tid = threadIdx.x;
    const int lane = tid & 31;
    const int gid  = lane >> 2;
    const int tig  = lane & 3;
    const int qb   = (tid >> 5) * 8;       // warp's first local query (8 per warp)
    const int s0j  = s0 - (W_ - 1);        // global row of local row 0
    const size_t headBase = (size_t)bb * S_ * HD + (size_t)h * D_;

    // ---- Issue K staging (group A), then V staging (group B), raw fp32 ----
#pragma unroll
    for (int i = 0; i < 8; i++) {
        const int idx = tid + i * NT;          // 0..1023
        const int r = idx >> 4, c4 = (idx & 15) << 2;
        const int j = s0j + r;
        const bool ok = (j >= 0) && (j < S_);
        const int jc = ok ? j : 0;
        const size_t off = headBase + (size_t)jc * HD + c4;
        cp16(smb + (uint32_t)(OFF_K + r * STRIDE + c4) * 4u, kg + off, ok ? 16 : 0);
    }
    asm volatile("cp.async.commit_group;" ::: "memory");
#pragma unroll
    for (int i = 0; i < 8; i++) {
        const int idx = tid + i * NT;
        const int r = idx >> 4, c4 = (idx & 15) << 2;
        const int j = s0j + r;
        const bool ok = (j >= 0) && (j < S_);
        const int jc = ok ? j : 0;
        const size_t off = headBase + (size_t)jc * HD + c4;
        cp16(smb + (uint32_t)(OFF_V + r * STRIDE + c4) * 4u, vg + off, ok ? 16 : 0);
    }
    asm volatile("cp.async.commit_group;" ::: "memory");

    // ---- Q fragments from gmem (rows 0..7 only; overlap cp.async) ----
    const float* qrow0 = qg + headBase + (size_t)(s0 + qb + gid) * HD;
    uint32_t qa[8][2];
#pragma unroll
    for (int kk = 0; kk < 8; kk++) {
        const int c = kk * 8 + tig;
        qa[kk][0] = tfb(qrow0[c]);
        qa[kk][1] = tfb(qrow0[c + 4]);
    }
    const float bq0 = bg[((size_t)bb * S_ + (s0 + qb + gid)) * H_ + h];
    if (tid < ROWS) {
        const int j = s0j + tid;
        a_sm[tid] = (j >= 0 && j < S_) ? ag[((size_t)bb * S_ + j) * H_ + h] : 0.f;
    }

    // ---- K ready (V still in flight); publish via barrier ----
    asm volatile("cp.async.wait_group 1;" ::: "memory");
    __syncthreads();

    // ---- Gate factors BEFORE GEMM1: gf = SCALE*sigmoid(a_l*b_q)*mask ----
    float gf[5][2];
#pragma unroll
    for (int nt = 0; nt < 5; nt++) {
        const int colbase = nt * 8 + 2 * tig;
        const float2 av2 = *(const float2*)(a_sm + qb + colbase);   // 8B-aligned
#pragma unroll
        for (int e = 0; e < 2; e++) {
            const int col = colbase + e;
            const int l   = qb + col;
            const int j   = s0j + l;
            const int d   = col - gid;
            const bool ok = (d >= 0) && (d < W_) && (j >= 0);
            const float av = e ? av2.y : av2.x;
            const float g = __fdividef(SCALE, 1.f + __expf(-av * bq0));
            gf[nt][e] = ok ? g : 0.f;
        }
    }

    const uint32_t zr = 0u;   // zero operand for unused fragment rows 8..15

    // ---- GEMM1: S[8,40] = Q @ K^T (inline cvt of raw K fragments) ----
    float acc[5][4] = {};
#pragma unroll
    for (int kk = 0; kk < 8; kk++) {
#pragma unroll
        for (int nt = 0; nt < 5; nt++) {
            const float* kp = ks + (qb + nt * 8 + gid) * STRIDE + kk * 8 + tig;
            mma_tf32(acc[nt], qa[kk][0], zr, qa[kk][1], zr,
                     tfb(kp[0]), tfb(kp[4]));
        }
    }

    // ---- Apply gates; D-frag -> A-frag via shuffles (rows 0..7) ----
    const int srcA = (lane & 28) | ((lane & 3) >> 1);
    const int srcB = srcA + 2;
    const bool odd = (lane & 1) != 0;
    uint32_t wa[5][2];
#pragma unroll
    for (int nt = 0; nt < 5; nt++) {
        const float w0 = f2tf32(acc[nt][0] * gf[nt][0]);
        const float w1 = f2tf32(acc[nt][1] * gf[nt][1]);
        const float s00 = __shfl_sync(0xffffffffu, w0, srcA);
        const float s10 = __shfl_sync(0xffffffffu, w1, srcA);
        const float s01 = __shfl_sync(0xffffffffu, w0, srcB);
        const float s11 = __shfl_sync(0xffffffffu, w1, srcB);
        wa[nt][0] = bits(odd ? s10 : s00);    // W[gid][nt*8+tig]
        wa[nt][1] = bits(odd ? s11 : s01);    // W[gid][nt*8+tig+4]
    }

    // ---- V ready; publish; GEMM2: O[8,64] = W[8,40] @ V[40,64] ----
    asm volatile("cp.async.wait_group 0;" ::: "memory");
    __syncthreads();

    float oacc[8][4] = {};
#pragma unroll
    for (int kk = 0; kk < 5; kk++) {
#pragma unroll
        for (int nt = 0; nt < 8; nt++) {
            const float* vp0 = vs + (qb + kk * 8 + tig) * STRIDE + nt * 8 + gid;
            const float* vp1 = vp0 + 4 * STRIDE;
            mma_tf32(oacc[nt], wa[kk][0], zr, wa[kk][1], zr,
                     tfb(vp0[0]), tfb(vp1[0]));
        }
    }

    // ---- Store O (rows 0..7 of each fragment) ----
    float* d0 = outg + headBase + (size_t)(s0 + qb + gid) * HD + 2 * tig;
#pragma unroll
    for (int nt = 0; nt < 8; nt++) {
        *(float2*)(d0 + nt * 8) = make_float2(oacc[nt][0], oacc[nt][1]);
    }
}

extern "C" void kernel_launch(void* const* d_in, const int* in_sizes, int n_in,
                              void* d_out, int out_size)
{
    const float* q = (const float*)d_in[0];
    const float* k = (const float*)d_in[1];
    const float* v = (const float*)d_in[2];
    const float* a = (const float*)d_in[3];
    const float* b = (const float*)d_in[4];
    float* out = (float*)d_out;

    const int smem = SMEM_FLOATS * (int)sizeof(float);   // 35072 B
    cudaFuncSetAttribute(swa_mma13_kernel,
                         cudaFuncAttributeMaxDynamicSharedMemorySize, smem);
    dim3 grid(S_ / TS, H_, B_);
    swa_mma13_kernel<<<grid, NT, smem>>>(q, k, v, a, b, out);
}

// round 17
// speedup vs baseline: 1.7450x; 1.0377x over previous
#include <cuda_runtime.h>
#include <cuda_fp16.h>
#include <cstdint>

// Sliding-window gated attention (W=32, D=64), sm_100-compatible.
// Per block: (b, h, 32 queries), 4 warps, each warp 8 queries x 40-col band.
//   stage: cp.async K (group A), V (group B) -> smem raw fp32
//   wait K -> convert own K chunks to fp16 tile -> barrier
//   gate factors (sigmoid only; SCALE folded into Q) -> GEMM1 fp16 m16n8k16
//   apply gates, D->A frag via shuffles (tf32)
//   wait V -> GEMM2 tf32 m16n8k8 (inline rna cvt)

constexpr int B_ = 2, S_ = 2048, H_ = 8, D_ = 64, W_ = 32;
constexpr int HD = H_ * D_;
constexpr int TS   = 32;
constexpr int NT   = 128;
constexpr int ROWS = 64;
constexpr int STRIDE = 68;         // fp32 tiles: ≡4 mod 32, conflict-free
constexpr int KS16  = 72;          // fp16 K tile stride (fp16 units): word stride 36 ≡ 4 mod 32
constexpr float SCALE = 0.125f;    // exact power of two; folded into Q

constexpr int OFF_K   = 0;
constexpr int SZ_K    = ROWS * STRIDE;           // 4352
constexpr int OFF_V   = OFF_K + SZ_K;
constexpr int OFF_A   = OFF_V + SZ_K;            // 64 floats
constexpr int OFF_K16 = OFF_A + ROWS;            // 64*72 fp16 = 2304 floats
constexpr int SMEM_FLOATS = OFF_K16 + (ROWS * KS16) / 2;   // 11072 floats = 44288 B

__device__ __forceinline__ float f2tf32(float x) {
    uint32_t r; asm("cvt.rna.tf32.f32 %0, %1;" : "=r"(r) : "f"(x));
    return __uint_as_float(r);
}
__device__ __forceinline__ uint32_t bits(float x) { return __float_as_uint(x); }
__device__ __forceinline__ uint32_t tfb(float x) {
    uint32_t r; asm("cvt.rna.tf32.f32 %0, %1;" : "=r"(r) : "f"(x));
    return r;
}
__device__ __forceinline__ uint32_t packh2(float lo, float hi) {
    const __half2 h = __floats2half2_rn(lo, hi);
    return *(const uint32_t*)&h;
}

__device__ __forceinline__ uint32_t smem_u32(const void* p) {
    uint32_t a;
    asm("{ .reg .u64 t; cvta.to.shared.u64 t, %1; cvt.u32.u64 %0, t; }" : "=r"(a) : "l"(p));
    return a;
}
__device__ __forceinline__ void cp16(uint32_t dst, const void* src, int srcsize) {
    asm volatile("cp.async.cg.shared.global [%0], [%1], 16, %2;"
                 :: "r"(dst), "l"(src), "r"(srcsize) : "memory");
}

__device__ __forceinline__ void mma_f16(float* d,
                                        uint32_t a0, uint32_t a1, uint32_t a2, uint32_t a3,
                                        uint32_t b0, uint32_t b1) {
    asm volatile("mma.sync.aligned.m16n8k16.row.col.f32.f16.f16.f32 "
                 "{%0,%1,%2,%3}, {%4,%5,%6,%7}, {%8,%9}, {%0,%1,%2,%3};"
                 : "+f"(d[0]), "+f"(d[1]), "+f"(d[2]), "+f"(d[3])
                 : "r"(a0), "r"(a1), "r"(a2), "r"(a3), "r"(b0), "r"(b1));
}
__device__ __forceinline__ void mma_tf32(float* d,
                                         uint32_t a0, uint32_t a1, uint32_t a2, uint32_t a3,
                                         uint32_t b0, uint32_t b1) {
    asm volatile("mma.sync.aligned.m16n8k8.row.col.f32.tf32.tf32.f32 "
                 "{%0,%1,%2,%3}, {%4,%5,%6,%7}, {%8,%9}, {%0,%1,%2,%3};"
                 : "+f"(d[0]), "+f"(d[1]), "+f"(d[2]), "+f"(d[3])
                 : "r"(a0), "r"(a1), "r"(a2), "r"(a3), "r"(b0), "r"(b1));
}

__global__ __launch_bounds__(NT, 5)
void swa_mma14_kernel(const float* __restrict__ qg,
                      const float* __restrict__ kg,
                      const float* __restrict__ vg,
                      const float* __restrict__ ag,
                      const float* __restrict__ bg,
                      float* __restrict__ outg)
{
    extern __shared__ float sm[];
    float* ks   = sm + OFF_K;
    float* vs   = sm + OFF_V;
    float* a_sm = sm + OFF_A;
    __half* k16 = (__half*)(sm + OFF_K16);
    const uint32_t smb = smem_u32(sm);

    const int s0  = blockIdx.x * TS;
    const int h   = blockIdx.y;
    const int bb  = blockIdx.z;
    const int tid = threadIdx.x;
    const int lane = tid & 31;
    const int gid  = lane >> 2;
    const int tig  = lane & 3;
    const int qb   = (tid >> 5) * 8;
    const int s0j  = s0 - (W_ - 1);
    const size_t headBase = (size_t)bb * S_ * HD + (size_t)h * D_;

    // ---- Issue K staging (group A), then V staging (group B), raw fp32 ----
#pragma unroll
    for (int i = 0; i < 8; i++) {
        const int idx = tid + i * NT;
        const int r = idx >> 4, c4 = (idx & 15) << 2;
        const int j = s0j + r;
        const bool ok = (j >= 0) && (j < S_);
        const size_t off = headBase + (size_t)(ok ? j : 0) * HD + c4;
        cp16(smb + (uint32_t)(OFF_K + r * STRIDE + c4) * 4u, kg + off, ok ? 16 : 0);
    }
    asm volatile("cp.async.commit_group;" ::: "memory");
#pragma unroll
    for (int i = 0; i < 8; i++) {
        const int idx = tid + i * NT;
        const int r = idx >> 4, c4 = (idx & 15) << 2;
        const int j = s0j + r;
        const bool ok = (j >= 0) && (j < S_);
        const size_t off = headBase + (size_t)(ok ? j : 0) * HD + c4;
        cp16(smb + (uint32_t)(OFF_V + r * STRIDE + c4) * 4u, vg + off, ok ? 16 : 0);
    }
    asm volatile("cp.async.commit_group;" ::: "memory");

    // ---- Q fragments: fp16, SCALE folded (exact x2^-3) ----
    const float* qrow0 = qg + headBase + (size_t)(s0 + qb + gid) * HD;
    uint32_t qa0[4], qa2[4];
#pragma unroll
    for (int kk = 0; kk < 4; kk++) {
        const float2 x = *(const float2*)(qrow0 + 16 * kk + 2 * tig);
        const float2 y = *(const float2*)(qrow0 + 16 * kk + 2 * tig + 8);
        qa0[kk] = packh2(x.x * SCALE, x.y * SCALE);
        qa2[kk] = packh2(y.x * SCALE, y.y * SCALE);
    }
    const float bq0 = bg[((size_t)bb * S_ + (s0 + qb + gid)) * H_ + h];
    if (tid < ROWS) {
        const int j = s0j + tid;
        a_sm[tid] = (j >= 0 && j < S_) ? ag[((size_t)bb * S_ + j) * H_ + h] : 0.f;
    }

    // ---- K ready; convert own chunks fp32 -> fp16 tile; publish ----
    asm volatile("cp.async.wait_group 1;" ::: "memory");
#pragma unroll
    for (int i = 0; i < 8; i++) {
        const int idx = tid + i * NT;
        const int r = idx >> 4, c4 = (idx & 15) << 2;
        const float4 f = *(const float4*)(ks + r * STRIDE + c4);
        const uint32_t h0 = packh2(f.x, f.y);
        const uint32_t h1 = packh2(f.z, f.w);
        *(uint2*)(k16 + r * KS16 + c4) = make_uint2(h0, h1);
    }
    __syncthreads();

    // ---- Gate factors (sigmoid only; SCALE already in Q) ----
    float gf[5][2];
#pragma unroll
    for (int nt = 0; nt < 5; nt++) {
        const int colbase = nt * 8 + 2 * tig;
        const float2 av2 = *(const float2*)(a_sm + qb + colbase);
#pragma unroll
        for (int e = 0; e < 2; e++) {
            const int col = colbase + e;
            const int l   = qb + col;
            const int j   = s0j + l;
            const int d   = col - gid;
            const bool ok = (d >= 0) && (d < W_) && (j >= 0);
            const float av = e ? av2.y : av2.x;
            const float g = __fdividef(1.f, 1.f + __expf(-av * bq0));
            gf[nt][e] = ok ? g : 0.f;
        }
    }

    const uint32_t zr = 0u;

    // ---- GEMM1 fp16: S[8,40] = Qs @ K^T (20 MMAs, LDS.32 B frags, no cvt) ----
    float acc[5][4] = {};
#pragma unroll
    for (int kk = 0; kk < 4; kk++) {
#pragma unroll
        for (int nt = 0; nt < 5; nt++) {
            const __half* kp = k16 + (qb + nt * 8 + gid) * KS16 + 16 * kk + 2 * tig;
            const uint32_t b0 = *(const uint32_t*)kp;
            const uint32_t b1 = *(const uint32_t*)(kp + 8);
            mma_f16(acc[nt], qa0[kk], zr, qa2[kk], zr, b0, b1);
        }
    }

    // ---- Apply gates; D-frag -> A-frag (tf32) via shuffles ----
    const int srcA = (lane & 28) | ((lane & 3) >> 1);
    const int srcB = srcA + 2;
    const bool odd = (lane & 1) != 0;
    uint32_t wa[5][2];
#pragma unroll
    for (int nt = 0; nt < 5; nt++) {
        const float w0 = f2tf32(acc[nt][0] * gf[nt][0]);
        const float w1 = f2tf32(acc[nt][1] * gf[nt][1]);
        const float s00 = __shfl_sync(0xffffffffu, w0, srcA);
        const float s10 = __shfl_sync(0xffffffffu, w1, srcA);
        const float s01 = __shfl_sync(0xffffffffu, w0, srcB);
        const float s11 = __shfl_sync(0xffffffffu, w1, srcB);
        wa[nt][0] = bits(odd ? s10 : s00);
        wa[nt][1] = bits(odd ? s11 : s01);
    }

    // ---- V ready; publish; GEMM2 tf32: O[8,64] = W[8,40] @ V[40,64] ----
    asm volatile("cp.async.wait_group 0;" ::: "memory");
    __syncthreads();

    float oacc[8][4] = {};
#pragma unroll
    for (int kk = 0; kk < 5; kk++) {
#pragma unroll
        for (int nt = 0; nt < 8; nt++) {
            const float* vp0 = vs + (qb + kk * 8 + tig) * STRIDE + nt * 8 + gid;
            const float* vp1 = vp0 + 4 * STRIDE;
            mma_tf32(oacc[nt], wa[kk][0], zr, wa[kk][1], zr,
                     tfb(vp0[0]), tfb(vp1[0]));
        }
    }

    // ---- Store O ----
    float* d0 = outg + headBase + (size_t)(s0 + qb + gid) * HD + 2 * tig;
#pragma unroll
    for (int nt = 0; nt < 8; nt++) {
        *(float2*)(d0 + nt * 8) = make_float2(oacc[nt][0], oacc[nt][1]);
    }
}

extern "C" void kernel_launch(void* const* d_in, const int* in_sizes, int n_in,
                              void* d_out, int out_size)
{
    const float* q = (const float*)d_in[0];
    const float* k = (const float*)d_in[1];
    const float* v = (const float*)d_in[2];
    const float* a = (const float*)d_in[3];
    const float* b = (const float*)d_in[4];
    float* out = (float*)d_out;

    const int smem = SMEM_FLOATS * (int)sizeof(float);   // 44288 B -> 5 CTAs/SM
    cudaFuncSetAttribute(swa_mma14_kernel,
                         cudaFuncAttributeMaxDynamicSharedMemorySize, smem);
    dim3 grid(S_ / TS, H_, B_);
    swa_mma14_kernel<<<grid, NT, smem>>>(q, k, v, a, b, out);
}